// round 1
// baseline (speedup 1.0000x reference)
#include <cuda_runtime.h>
#include <cuda_bf16.h>

// y[n] = beta_0 + sum_{i<7,j<64} x[n,i,j] * w[i,j],  w = gamma^T @ alpha (rank 64)
// x: [131072, 7, 64] fp32.  HBM-bound: 235 MB read.

#define N_GAMMA 7
#define N_ALPHA 64
#define RANK    64
#define W_ELEMS (N_GAMMA * N_ALPHA)   // 448
#define W_F4    (W_ELEMS / 4)         // 112

__device__ float g_w[W_ELEMS];

// Collapse CP factors into the 7x64 weight matrix. One block, 448 threads.
__global__ void prep_w_kernel(const float* __restrict__ gamma,   // [64,7]
                              const float* __restrict__ alpha)   // [64,64]
{
    int idx = threadIdx.x;
    if (idx >= W_ELEMS) return;
    int i = idx / N_ALPHA;   // gamma column
    int j = idx % N_ALPHA;   // alpha column
    float s = 0.0f;
#pragma unroll
    for (int r = 0; r < RANK; r++) {
        s = fmaf(gamma[r * N_GAMMA + i], alpha[r * N_ALPHA + j], s);
    }
    g_w[idx] = s;
}

// One warp per row. 256 threads = 8 rows per block.
__global__ __launch_bounds__(256) void cp_dot_kernel(
    const float* __restrict__ x,
    const float* __restrict__ beta0_p,
    float* __restrict__ y,
    int n_rows)
{
    __shared__ float4 sw[W_F4];

    // Stage w into shared (stride-1, conflict-free on reads).
    const float4* wg = reinterpret_cast<const float4*>(g_w);
    for (int t = threadIdx.x; t < W_F4; t += blockDim.x)
        sw[t] = wg[t];
    __syncthreads();

    int warp = threadIdx.x >> 5;
    int lane = threadIdx.x & 31;
    int n = blockIdx.x * (blockDim.x >> 5) + warp;
    if (n >= n_rows) return;

    const float4* xr = reinterpret_cast<const float4*>(x + (size_t)n * W_ELEMS);

    float acc = 0.0f;
    // 112 float4 per row: 3 full warp iterations (96) + 16-lane tail.
#pragma unroll
    for (int t = 0; t < 3; t++) {
        int k = lane + 32 * t;
        float4 v = xr[k];
        float4 w4 = sw[k];
        acc = fmaf(v.x, w4.x, acc);
        acc = fmaf(v.y, w4.y, acc);
        acc = fmaf(v.z, w4.z, acc);
        acc = fmaf(v.w, w4.w, acc);
    }
    if (lane < 16) {
        int k = 96 + lane;
        float4 v = xr[k];
        float4 w4 = sw[k];
        acc = fmaf(v.x, w4.x, acc);
        acc = fmaf(v.y, w4.y, acc);
        acc = fmaf(v.z, w4.z, acc);
        acc = fmaf(v.w, w4.w, acc);
    }

    // Warp reduction.
#pragma unroll
    for (int o = 16; o > 0; o >>= 1)
        acc += __shfl_xor_sync(0xFFFFFFFFu, acc, o);

    if (lane == 0)
        y[n] = beta0_p[0] + acc;
}

extern "C" void kernel_launch(void* const* d_in, const int* in_sizes, int n_in,
                              void* d_out, int out_size)
{
    const float* x     = (const float*)d_in[0];  // [131072*448]
    const float* beta0 = (const float*)d_in[1];  // [1]
    const float* gamma = (const float*)d_in[2];  // [64*7]
    const float* alpha = (const float*)d_in[3];  // [64*64]
    float* y = (float*)d_out;

    int n_rows = in_sizes[0] / W_ELEMS;

    prep_w_kernel<<<1, W_ELEMS>>>(gamma, alpha);

    int rows_per_block = 256 / 32;  // 8
    int grid = (n_rows + rows_per_block - 1) / rows_per_block;
    cp_dot_kernel<<<grid, 256>>>(x, beta0, y, n_rows);
}